// round 3
// baseline (speedup 1.0000x reference)
#include <cuda_runtime.h>
#include <math.h>

// Problem constants (fixed by reference)
#define T_STEPS 128
#define MATPTS  16
#define PTS_PER_THREAD 2
#define THREADS_PER_B  (MATPTS / PTS_PER_THREAD)   // 8

// Material constants, derived in double precision at compile time
static constexpr double E_MOD_D = 3130.0;
static constexpr double NU_D    = 0.37;
static constexpr double MU_D    = E_MOD_D / (2.0 * (1.0 + NU_D));
static constexpr double LAM_D   = E_MOD_D * NU_D / ((1.0 + NU_D) * (1.0 - 2.0 * NU_D));
static constexpr double SIGY_D  = 64.8;
static constexpr double H_D     = 300.0;

static constexpr float MU_F     = (float)MU_D;
static constexpr float TWO_MU_F = (float)(2.0 * MU_D);
static constexpr float LAM_F    = (float)LAM_D;
static constexpr float SIGY_F   = (float)SIGY_D;
static constexpr float H_F      = (float)H_D;
static constexpr float KINV_F   = (float)(1.0 / (3.0 * MU_D + H_D));

__global__ void __launch_bounds__(256)
prnn_j2_kernel(const float* __restrict__ x,
               const float* __restrict__ W1,
               const float* __restrict__ W2,
               float* __restrict__ out,
               int B)
{
    const int tid = blockIdx.x * blockDim.x + threadIdx.x;
    const int b   = tid >> 3;           // batch element
    const int sub = tid & 7;            // sub-lane within the 8-thread group
    if (b >= B) return;

    // ---- Load per-thread weight slices into registers -------------------
    // Thread handles material points m = 2*sub + k, k in {0,1}.
    float w1[PTS_PER_THREAD][3][3];     // w1[k][j][f]: eps_j = sum_f x_f * W1[3m+j, f]
    float w2[PTS_PER_THREAD][3][3];     // w2[k][o][j] = softplus(W2[o, 3m+j])
    #pragma unroll
    for (int k = 0; k < PTS_PER_THREAD; ++k) {
        const int m = sub * PTS_PER_THREAD + k;
        #pragma unroll
        for (int j = 0; j < 3; ++j) {
            #pragma unroll
            for (int f = 0; f < 3; ++f)
                w1[k][j][f] = __ldg(&W1[(3 * m + j) * 3 + f]);
        }
        #pragma unroll
        for (int o = 0; o < 3; ++o) {
            #pragma unroll
            for (int j = 0; j < 3; ++j) {
                float w = __ldg(&W2[o * 48 + 3 * m + j]);
                w2[k][o][j] = log1pf(expf(w));   // softplus (one-time)
            }
        }
    }

    // ---- Committed history (lives in registers for the whole sequence) --
    float pxx[PTS_PER_THREAD], pyy[PTS_PER_THREAD], pzz[PTS_PER_THREAD],
          pxy[PTS_PER_THREAD], al[PTS_PER_THREAD];
    #pragma unroll
    for (int k = 0; k < PTS_PER_THREAD; ++k) {
        pxx[k] = 0.f; pyy[k] = 0.f; pzz[k] = 0.f; pxy[k] = 0.f; al[k] = 0.f;
    }

    const float* xb = x   + (size_t)b * (T_STEPS * 3);
    float*       ob = out + (size_t)b * (T_STEPS * 3);

    #pragma unroll 1
    for (int t = 0; t < T_STEPS; ++t) {
        const float ex = xb[3 * t + 0];
        const float ey = xb[3 * t + 1];
        const float eg = xb[3 * t + 2];

        float a0 = 0.f, a1 = 0.f, a2 = 0.f;

        #pragma unroll
        for (int k = 0; k < PTS_PER_THREAD; ++k) {
            // fc1: per-point strain
            const float e0 = fmaf(ex, w1[k][0][0], fmaf(ey, w1[k][0][1], eg * w1[k][0][2]));
            const float e1 = fmaf(ex, w1[k][1][0], fmaf(ey, w1[k][1][1], eg * w1[k][1][2]));
            const float e2 = fmaf(ex, w1[k][2][0], fmaf(ey, w1[k][2][1], eg * w1[k][2][2]));

            // elastic predictor
            const float eexx = e0 - pxx[k];
            const float eeyy = e1 - pyy[k];
            const float eezz = -pzz[k];
            const float eexy = fmaf(0.5f, e2, -pxy[k]);
            const float tr   = eexx + eeyy + eezz;
            const float ltr  = LAM_F * tr;
            const float sxx  = fmaf(TWO_MU_F, eexx, ltr);
            const float syy  = fmaf(TWO_MU_F, eeyy, ltr);
            const float szz  = fmaf(TWO_MU_F, eezz, ltr);
            const float sxy  = TWO_MU_F * eexy;

            const float pm  = (sxx + syy + szz) * (1.0f / 3.0f);
            const float dxx = sxx - pm;
            const float dyy = syy - pm;
            const float dzz = szz - pm;

            const float s2 = fmaf(dxx, dxx, fmaf(dyy, dyy,
                              fmaf(dzz, dzz, 2.0f * sxy * sxy)));
            const float q  = sqrtf(1.5f * s2);

            // radial return (closed form)
            const float f  = q - fmaf(H_F, al[k], SIGY_F);
            const float dg = fmaxf(f, 0.0f) * KINV_F;
            const float c  = dg * __fdividef(1.5f, fmaxf(q, 1e-12f)); // 1.5*dgam/qs
            al[k] += dg;

            // commit plastic strain
            pxx[k] = fmaf(c, dxx, pxx[k]);
            pyy[k] = fmaf(c, dyy, pyy[k]);
            pzz[k] = fmaf(c, dzz, pzz[k]);
            pxy[k] = fmaf(c, sxy, pxy[k]);

            // corrected stress (xx, yy, xy)
            const float c2  = TWO_MU_F * c;
            const float oxx = fmaf(-c2, dxx, sxx);
            const float oyy = fmaf(-c2, dyy, syy);
            const float oxy = fmaf(-c2, sxy, sxy);

            // fc2 partial (softplus weights)
            a0 = fmaf(oxx, w2[k][0][0], fmaf(oyy, w2[k][0][1], fmaf(oxy, w2[k][0][2], a0)));
            a1 = fmaf(oxx, w2[k][1][0], fmaf(oyy, w2[k][1][1], fmaf(oxy, w2[k][1][2], a1)));
            a2 = fmaf(oxx, w2[k][2][0], fmaf(oyy, w2[k][2][1], fmaf(oxy, w2[k][2][2], a2)));
        }

        // reduce the 8-lane group (lanes of one batch element are contiguous)
        a0 += __shfl_xor_sync(0xffffffffu, a0, 1);
        a1 += __shfl_xor_sync(0xffffffffu, a1, 1);
        a2 += __shfl_xor_sync(0xffffffffu, a2, 1);
        a0 += __shfl_xor_sync(0xffffffffu, a0, 2);
        a1 += __shfl_xor_sync(0xffffffffu, a1, 2);
        a2 += __shfl_xor_sync(0xffffffffu, a2, 2);
        a0 += __shfl_xor_sync(0xffffffffu, a0, 4);
        a1 += __shfl_xor_sync(0xffffffffu, a1, 4);
        a2 += __shfl_xor_sync(0xffffffffu, a2, 4);

        if (sub == 0) {
            ob[3 * t + 0] = a0;
            ob[3 * t + 1] = a1;
            ob[3 * t + 2] = a2;
        }
    }
}

extern "C" void kernel_launch(void* const* d_in, const int* in_sizes, int n_in,
                              void* d_out, int out_size)
{
    const float* x  = (const float*)d_in[0];   // [B, T, 3]
    const float* W1 = (const float*)d_in[1];   // [48, 3]
    const float* W2 = (const float*)d_in[2];   // [3, 48]
    float* out      = (float*)d_out;           // [B, T, 3]

    const int B = in_sizes[0] / (T_STEPS * 3);
    const int total_threads = B * THREADS_PER_B;
    const int block = 256;
    const int grid  = (total_threads + block - 1) / block;

    prnn_j2_kernel<<<grid, block>>>(x, W1, W2, out, B);
}

// round 4
// speedup vs baseline: 1.1643x; 1.1643x over previous
#include <cuda_runtime.h>
#include <math.h>

// Problem constants (fixed by reference)
#define T_STEPS 128
#define MATPTS  16
#define PPT     4                    // material points per thread
#define TPB     (MATPTS / PPT)       // threads per batch element = 4
#define BLOCK   64

// Material constants, derived in double precision at compile time
static constexpr double E_MOD_D = 3130.0;
static constexpr double NU_D    = 0.37;
static constexpr double MU_D    = E_MOD_D / (2.0 * (1.0 + NU_D));
static constexpr double LAM_D   = E_MOD_D * NU_D / ((1.0 + NU_D) * (1.0 - 2.0 * NU_D));
static constexpr double SIGY_D  = 64.8;
static constexpr double H_D     = 300.0;

static constexpr float TWO_MU_F = (float)(2.0 * MU_D);
static constexpr float LAM_F    = (float)LAM_D;
static constexpr float SIGY_F   = (float)SIGY_D;
static constexpr float H_F      = (float)H_D;
static constexpr float KINV_F   = (float)(1.0 / (3.0 * MU_D + H_D));

__global__ void __launch_bounds__(BLOCK)
prnn_j2_kernel(const float* __restrict__ x,
               const float* __restrict__ W1,
               const float* __restrict__ W2,
               float* __restrict__ out,
               int B)
{
    const int tid = blockIdx.x * BLOCK + threadIdx.x;
    const int b   = tid >> 2;           // batch element
    const int sub = tid & 3;            // sub-lane within the 4-thread group
    if (b >= B) return;

    // ---- Per-thread weight slices in registers --------------------------
    // Thread handles material points m = 4*sub + k, k in 0..3.
    float w1[PPT][3][3];     // eps_j = sum_f x_f * W1[3m+j, f]
    float w2[PPT][3][3];     // w2[k][o][j] = softplus(W2[o, 3m+j])
    #pragma unroll
    for (int k = 0; k < PPT; ++k) {
        const int m = sub * PPT + k;
        #pragma unroll
        for (int j = 0; j < 3; ++j) {
            #pragma unroll
            for (int f = 0; f < 3; ++f)
                w1[k][j][f] = __ldg(&W1[(3 * m + j) * 3 + f]);
        }
        #pragma unroll
        for (int o = 0; o < 3; ++o) {
            #pragma unroll
            for (int j = 0; j < 3; ++j) {
                float w = __ldg(&W2[o * 48 + 3 * m + j]);
                w2[k][o][j] = log1pf(expf(w));   // softplus (one-time)
            }
        }
    }

    // ---- Committed history (registers for the whole sequence) -----------
    // pzz is eliminated: deviatoric flow is traceless, so pzz == -(pxx+pyy).
    float pxx[PPT], pyy[PPT], pxy[PPT], al[PPT];
    #pragma unroll
    for (int k = 0; k < PPT; ++k) { pxx[k]=0.f; pyy[k]=0.f; pxy[k]=0.f; al[k]=0.f; }

    const float* xp = x   + (size_t)b * (T_STEPS * 3);
    float*       op = out + (size_t)b * (T_STEPS * 3);

    // software-pipelined x loads
    float ex = xp[0], ey = xp[1], eg = xp[2];

    #pragma unroll 1
    for (int t = 0; t < T_STEPS; ++t) {
        float nex = 0.f, ney = 0.f, neg = 0.f;
        if (t + 1 < T_STEPS) {
            nex = xp[3 * t + 3];
            ney = xp[3 * t + 4];
            neg = xp[3 * t + 5];
        }

        float a0 = 0.f, a1 = 0.f, a2 = 0.f;

        #pragma unroll
        for (int k = 0; k < PPT; ++k) {
            // fc1: per-point strain
            const float e0 = fmaf(ex, w1[k][0][0], fmaf(ey, w1[k][0][1], eg * w1[k][0][2]));
            const float e1 = fmaf(ex, w1[k][1][0], fmaf(ey, w1[k][1][1], eg * w1[k][1][2]));
            const float e2 = fmaf(ex, w1[k][2][0], fmaf(ey, w1[k][2][1], eg * w1[k][2][2]));

            // elastic predictor (pzz = -(pxx+pyy), tr = e0+e1 exactly)
            const float spp  = pxx[k] + pyy[k];
            const float eexx = e0 - pxx[k];
            const float eeyy = e1 - pyy[k];
            const float eexy = fmaf(0.5f, e2, -pxy[k]);
            const float ltr  = LAM_F * (e0 + e1);
            const float sxx  = fmaf(TWO_MU_F, eexx, ltr);
            const float syy  = fmaf(TWO_MU_F, eeyy, ltr);
            const float szz  = fmaf(TWO_MU_F, spp,  ltr);
            const float sxy  = TWO_MU_F * eexy;

            const float pm  = (sxx + syy + szz) * (1.0f / 3.0f);
            const float dxx = sxx - pm;
            const float dyy = syy - pm;

            // q^2 = 1.5*(dxx^2+dyy^2+dzz^2+2 sxy^2) = 3*(dxx^2+dyy^2+dxx*dyy+sxy^2)
            const float u   = fmaf(dxx, dxx, fmaf(dyy, dyy, fmaf(dxx, dyy, sxy * sxy)));
            const float s2c = fmaxf(3.0f * u, 1e-24f);
            const float r   = rsqrtf(s2c);       // 1 MUFU gives both q and 1/q
            const float q   = s2c * r;

            // radial return (closed form)
            const float f  = q - fmaf(H_F, al[k], SIGY_F);
            const float dg = fmaxf(f, 0.0f) * KINV_F;
            al[k] += dg;
            const float c  = (1.5f * dg) * r;    // = 1.5*dgam/q

            // commit plastic strain
            pxx[k] = fmaf(c, dxx, pxx[k]);
            pyy[k] = fmaf(c, dyy, pyy[k]);
            pxy[k] = fmaf(c, sxy, pxy[k]);

            // corrected stress (xx, yy, xy)
            const float c2  = TWO_MU_F * c;
            const float oxx = fmaf(-c2, dxx, sxx);
            const float oyy = fmaf(-c2, dyy, syy);
            const float oxy = fmaf(-c2, sxy, sxy);

            // fc2 partial (softplus weights)
            a0 = fmaf(oxx, w2[k][0][0], fmaf(oyy, w2[k][0][1], fmaf(oxy, w2[k][0][2], a0)));
            a1 = fmaf(oxx, w2[k][1][0], fmaf(oyy, w2[k][1][1], fmaf(oxy, w2[k][1][2], a1)));
            a2 = fmaf(oxx, w2[k][2][0], fmaf(oyy, w2[k][2][1], fmaf(oxy, w2[k][2][2], a2)));
        }

        // reduce the 4-lane group (2 xor rounds)
        a0 += __shfl_xor_sync(0xffffffffu, a0, 1);
        a1 += __shfl_xor_sync(0xffffffffu, a1, 1);
        a2 += __shfl_xor_sync(0xffffffffu, a2, 1);
        a0 += __shfl_xor_sync(0xffffffffu, a0, 2);
        a1 += __shfl_xor_sync(0xffffffffu, a1, 2);
        a2 += __shfl_xor_sync(0xffffffffu, a2, 2);

        // lanes 0..2 each store one component (1 predicated STG instead of 3)
        const float oval = (sub == 0) ? a0 : ((sub == 1) ? a1 : a2);
        if (sub < 3) op[3 * t + sub] = oval;

        ex = nex; ey = ney; eg = neg;
    }
}

extern "C" void kernel_launch(void* const* d_in, const int* in_sizes, int n_in,
                              void* d_out, int out_size)
{
    const float* x  = (const float*)d_in[0];   // [B, T, 3]
    const float* W1 = (const float*)d_in[1];   // [48, 3]
    const float* W2 = (const float*)d_in[2];   // [3, 48]
    float* out      = (float*)d_out;           // [B, T, 3]

    const int B = in_sizes[0] / (T_STEPS * 3);
    const int total_threads = B * TPB;
    const int grid = (total_threads + BLOCK - 1) / BLOCK;

    prnn_j2_kernel<<<grid, BLOCK>>>(x, W1, W2, out, B);
}

// round 5
// speedup vs baseline: 1.1682x; 1.0034x over previous
#include <cuda_runtime.h>
#include <math.h>

// Problem constants (fixed by reference)
#define T_STEPS 128
#define MATPTS  16
#define PPT     4                    // material points per thread
#define TPB     (MATPTS / PPT)       // threads per batch element = 4
#define BLOCK   64

// Material constants, derived in double precision at compile time
static constexpr double E_MOD_D = 3130.0;
static constexpr double NU_D    = 0.37;
static constexpr double MU_D    = E_MOD_D / (2.0 * (1.0 + NU_D));
static constexpr double LAM_D   = E_MOD_D * NU_D / ((1.0 + NU_D) * (1.0 - 2.0 * NU_D));
static constexpr double SIGY_D  = 64.8;
static constexpr double H_D     = 300.0;

static constexpr float TWO_MU_F = (float)(2.0 * MU_D);
static constexpr float LAM_F    = (float)LAM_D;
static constexpr float SIGY_F   = (float)SIGY_D;
static constexpr float H_F      = (float)H_D;
static constexpr float KINV_F   = (float)(1.0 / (3.0 * MU_D + H_D));

__global__ void __launch_bounds__(BLOCK)
prnn_j2_kernel(const float* __restrict__ x,
               const float* __restrict__ W1,
               const float* __restrict__ W2,
               float* __restrict__ out,
               int B)
{
    const int tid = blockIdx.x * BLOCK + threadIdx.x;
    const int b   = tid >> 2;           // batch element
    const int sub = tid & 3;            // sub-lane within the 4-thread group
    if (b >= B) return;

    // ---- Per-thread weight slices in registers --------------------------
    // Thread handles material points m = 4*sub + k, k in 0..3.
    float w1[PPT][3][3];     // eps_j = sum_f x_f * W1[3m+j, f]
    float w2[PPT][3][3];     // w2[k][o][j] = softplus(W2[o, 3m+j])
    #pragma unroll
    for (int k = 0; k < PPT; ++k) {
        const int m = sub * PPT + k;
        #pragma unroll
        for (int j = 0; j < 3; ++j) {
            #pragma unroll
            for (int f = 0; f < 3; ++f)
                w1[k][j][f] = __ldg(&W1[(3 * m + j) * 3 + f]);
        }
        #pragma unroll
        for (int o = 0; o < 3; ++o) {
            #pragma unroll
            for (int j = 0; j < 3; ++j) {
                float w = __ldg(&W2[o * 48 + 3 * m + j]);
                w2[k][o][j] = log1pf(expf(w));   // softplus (one-time)
            }
        }
    }

    // ---- Committed history (registers for the whole sequence) -----------
    // pzz is eliminated: deviatoric flow is traceless, so pzz == -(pxx+pyy).
    float pxx[PPT], pyy[PPT], pxy[PPT], al[PPT];
    #pragma unroll
    for (int k = 0; k < PPT; ++k) { pxx[k]=0.f; pyy[k]=0.f; pxy[k]=0.f; al[k]=0.f; }

    const float* xp = x   + (size_t)b * (T_STEPS * 3);
    float*       op = out + (size_t)b * (T_STEPS * 3);

    // software-pipelined x loads
    float ex = xp[0], ey = xp[1], eg = xp[2];

    #pragma unroll 1
    for (int t = 0; t < T_STEPS; ++t) {
        float nex = 0.f, ney = 0.f, neg = 0.f;
        if (t + 1 < T_STEPS) {
            nex = xp[3 * t + 3];
            ney = xp[3 * t + 4];
            neg = xp[3 * t + 5];
        }

        float a0 = 0.f, a1 = 0.f, a2 = 0.f;

        #pragma unroll
        for (int k = 0; k < PPT; ++k) {
            // fc1: per-point strain
            const float e0 = fmaf(ex, w1[k][0][0], fmaf(ey, w1[k][0][1], eg * w1[k][0][2]));
            const float e1 = fmaf(ex, w1[k][1][0], fmaf(ey, w1[k][1][1], eg * w1[k][1][2]));
            const float e2 = fmaf(ex, w1[k][2][0], fmaf(ey, w1[k][2][1], eg * w1[k][2][2]));

            // elastic predictor (pzz = -(pxx+pyy), tr = e0+e1 exactly)
            const float spp  = pxx[k] + pyy[k];
            const float eexx = e0 - pxx[k];
            const float eeyy = e1 - pyy[k];
            const float eexy = fmaf(0.5f, e2, -pxy[k]);
            const float ltr  = LAM_F * (e0 + e1);
            const float sxx  = fmaf(TWO_MU_F, eexx, ltr);
            const float syy  = fmaf(TWO_MU_F, eeyy, ltr);
            const float szz  = fmaf(TWO_MU_F, spp,  ltr);
            const float sxy  = TWO_MU_F * eexy;

            const float pm  = (sxx + syy + szz) * (1.0f / 3.0f);
            const float dxx = sxx - pm;
            const float dyy = syy - pm;

            // q^2 = 1.5*(dxx^2+dyy^2+dzz^2+2 sxy^2) = 3*(dxx^2+dyy^2+dxx*dyy+sxy^2)
            const float u   = fmaf(dxx, dxx, fmaf(dyy, dyy, fmaf(dxx, dyy, sxy * sxy)));
            const float s2c = fmaxf(3.0f * u, 1e-24f);
            const float r   = rsqrtf(s2c);       // 1 MUFU gives both q and 1/q
            const float q   = s2c * r;

            // radial return (closed form)
            const float f  = q - fmaf(H_F, al[k], SIGY_F);
            const float dg = fmaxf(f, 0.0f) * KINV_F;
            al[k] += dg;
            const float c  = (1.5f * dg) * r;    // = 1.5*dgam/q

            // commit plastic strain
            pxx[k] = fmaf(c, dxx, pxx[k]);
            pyy[k] = fmaf(c, dyy, pyy[k]);
            pxy[k] = fmaf(c, sxy, pxy[k]);

            // corrected stress (xx, yy, xy)
            const float c2  = TWO_MU_F * c;
            const float oxx = fmaf(-c2, dxx, sxx);
            const float oyy = fmaf(-c2, dyy, syy);
            const float oxy = fmaf(-c2, sxy, sxy);

            // fc2 partial (softplus weights)
            a0 = fmaf(oxx, w2[k][0][0], fmaf(oyy, w2[k][0][1], fmaf(oxy, w2[k][0][2], a0)));
            a1 = fmaf(oxx, w2[k][1][0], fmaf(oyy, w2[k][1][1], fmaf(oxy, w2[k][1][2], a1)));
            a2 = fmaf(oxx, w2[k][2][0], fmaf(oyy, w2[k][2][1], fmaf(oxy, w2[k][2][2], a2)));
        }

        // reduce the 4-lane group (2 xor rounds)
        a0 += __shfl_xor_sync(0xffffffffu, a0, 1);
        a1 += __shfl_xor_sync(0xffffffffu, a1, 1);
        a2 += __shfl_xor_sync(0xffffffffu, a2, 1);
        a0 += __shfl_xor_sync(0xffffffffu, a0, 2);
        a1 += __shfl_xor_sync(0xffffffffu, a1, 2);
        a2 += __shfl_xor_sync(0xffffffffu, a2, 2);

        // lanes 0..2 each store one component (1 predicated STG instead of 3)
        const float oval = (sub == 0) ? a0 : ((sub == 1) ? a1 : a2);
        if (sub < 3) op[3 * t + sub] = oval;

        ex = nex; ey = ney; eg = neg;
    }
}

extern "C" void kernel_launch(void* const* d_in, const int* in_sizes, int n_in,
                              void* d_out, int out_size)
{
    const float* x  = (const float*)d_in[0];   // [B, T, 3]
    const float* W1 = (const float*)d_in[1];   // [48, 3]
    const float* W2 = (const float*)d_in[2];   // [3, 48]
    float* out      = (float*)d_out;           // [B, T, 3]

    const int B = in_sizes[0] / (T_STEPS * 3);
    const int total_threads = B * TPB;
    const int grid = (total_threads + BLOCK - 1) / BLOCK;

    prnn_j2_kernel<<<grid, BLOCK>>>(x, W1, W2, out, B);
}

// round 6
// speedup vs baseline: 1.2142x; 1.0394x over previous
#include <cuda_runtime.h>
#include <math.h>

// Problem constants (fixed by reference)
#define T_STEPS 128
#define MATPTS  16
#define PPT     4                    // material points per thread (2 packed pairs)
#define TPB     (MATPTS / PPT)       // threads per batch element = 4
#define BLOCK   64

// Material constants, derived in double precision at compile time
static constexpr double E_MOD_D = 3130.0;
static constexpr double NU_D    = 0.37;
static constexpr double MU_D    = E_MOD_D / (2.0 * (1.0 + NU_D));
static constexpr double LAM_D   = E_MOD_D * NU_D / ((1.0 + NU_D) * (1.0 - 2.0 * NU_D));
static constexpr double SIGY_D  = 64.8;
static constexpr double H_D     = 300.0;

static constexpr float TWO_MU_F = (float)(2.0 * MU_D);
static constexpr float LAM_F    = (float)LAM_D;
static constexpr float SIGY_F   = (float)SIGY_D;
static constexpr float H_F      = (float)H_D;
static constexpr float KINV_F   = (float)(1.0 / (3.0 * MU_D + H_D));

// ---- packed fp32x2 helpers (sm_100+ only; FFMA2/FADD2/FMUL2 in SASS) ------
typedef unsigned long long u64t;
struct F2 { u64t v; };

__device__ __forceinline__ F2 f2pack(float lo, float hi) {
    F2 r; asm("mov.b64 %0, {%1, %2};" : "=l"(r.v) : "f"(lo), "f"(hi)); return r;
}
__device__ __forceinline__ void f2unpack(F2 a, float& lo, float& hi) {
    asm("mov.b64 {%0, %1}, %2;" : "=f"(lo), "=f"(hi) : "l"(a.v));
}
__device__ __forceinline__ F2 f2fma(F2 a, F2 b, F2 c) {
    F2 r; asm("fma.rn.f32x2 %0, %1, %2, %3;" : "=l"(r.v) : "l"(a.v), "l"(b.v), "l"(c.v)); return r;
}
__device__ __forceinline__ F2 f2add(F2 a, F2 b) {
    F2 r; asm("add.rn.f32x2 %0, %1, %2;" : "=l"(r.v) : "l"(a.v), "l"(b.v)); return r;
}
__device__ __forceinline__ F2 f2mul(F2 a, F2 b) {
    F2 r; asm("mul.rn.f32x2 %0, %1, %2;" : "=l"(r.v) : "l"(a.v), "l"(b.v)); return r;
}
__device__ __forceinline__ F2 f2zero() { F2 r; r.v = 0ULL; return r; }

__global__ void __launch_bounds__(BLOCK)
prnn_j2_kernel(const float* __restrict__ x,
               const float* __restrict__ W1,
               const float* __restrict__ W2,
               float* __restrict__ out,
               int B)
{
    const int tid = blockIdx.x * BLOCK + threadIdx.x;
    const int b   = tid >> 2;           // batch element
    const int sub = tid & 3;            // sub-lane within the 4-thread group
    if (b >= B) return;

    // ---- Packed per-thread weight slices --------------------------------
    // Thread handles points m = 4*sub + {0..3}; pair p packs points (2p, 2p+1).
    F2 w1p[2][3][3];   // eps_j = sum_f x_f * W1[3m+j, f]   (both pair slots)
    F2 w2p[2][3][3];   // softplus(W2[o, 3m+j])
    #pragma unroll
    for (int p = 0; p < 2; ++p) {
        const int mlo = sub * PPT + 2 * p;
        #pragma unroll
        for (int j = 0; j < 3; ++j)
            #pragma unroll
            for (int f = 0; f < 3; ++f)
                w1p[p][j][f] = f2pack(__ldg(&W1[(3 * mlo + j) * 3 + f]),
                                      __ldg(&W1[(3 * (mlo + 1) + j) * 3 + f]));
        #pragma unroll
        for (int o = 0; o < 3; ++o)
            #pragma unroll
            for (int j = 0; j < 3; ++j) {
                float wl = __ldg(&W2[o * 48 + 3 * mlo + j]);
                float wh = __ldg(&W2[o * 48 + 3 * (mlo + 1) + j]);
                w2p[p][o][j] = f2pack(log1pf(expf(wl)), log1pf(expf(wh)));
            }
    }

    // ---- Packed constants ------------------------------------------------
    const F2 TWOMU2  = f2pack(TWO_MU_F,  TWO_MU_F);
    const F2 NTWOMU2 = f2pack(-TWO_MU_F, -TWO_MU_F);
    const F2 LAM2    = f2pack(LAM_F,     LAM_F);
    const F2 HALF2   = f2pack(0.5f,      0.5f);
    const F2 NTHIRD2 = f2pack(-1.0f/3.0f, -1.0f/3.0f);
    const F2 THREE2  = f2pack(3.0f,      3.0f);
    const F2 H2      = f2pack(H_F,       H_F);
    const F2 SIGY2   = f2pack(SIGY_F,    SIGY_F);

    // ---- Committed history, negated & packed (npxx = -pxx etc.) ----------
    // pzz eliminated (traceless flow: pzz = -(pxx+pyy)).
    F2 npxx[2], npyy[2], npxy[2], al2[2];
    #pragma unroll
    for (int p = 0; p < 2; ++p) {
        npxx[p] = f2zero(); npyy[p] = f2zero(); npxy[p] = f2zero(); al2[p] = f2zero();
    }

    const float* xp = x   + (size_t)b * (T_STEPS * 3);
    float*       op = out + (size_t)b * (T_STEPS * 3);

    // software-pipelined x loads
    float ex = xp[0], ey = xp[1], eg = xp[2];

    #pragma unroll 1
    for (int t = 0; t < T_STEPS; ++t) {
        float nex = 0.f, ney = 0.f, neg_ = 0.f;
        if (t + 1 < T_STEPS) {
            nex  = xp[3 * t + 3];
            ney  = xp[3 * t + 4];
            neg_ = xp[3 * t + 5];
        }

        const F2 ex2 = f2pack(ex, ex);
        const F2 ey2 = f2pack(ey, ey);
        const F2 eg2 = f2pack(eg, eg);

        F2 a0 = f2zero(), a1 = f2zero(), a2 = f2zero();

        #pragma unroll
        for (int p = 0; p < 2; ++p) {
            // fc1: per-point strain (packed across the pair)
            const F2 e0 = f2fma(ex2, w1p[p][0][0], f2fma(ey2, w1p[p][0][1], f2mul(eg2, w1p[p][0][2])));
            const F2 e1 = f2fma(ex2, w1p[p][1][0], f2fma(ey2, w1p[p][1][1], f2mul(eg2, w1p[p][1][2])));
            const F2 e2 = f2fma(ex2, w1p[p][2][0], f2fma(ey2, w1p[p][2][1], f2mul(eg2, w1p[p][2][2])));

            // elastic predictor (state negated: eexx = e0 + npxx)
            const F2 eexx = f2add(e0, npxx[p]);
            const F2 eeyy = f2add(e1, npyy[p]);
            const F2 eexy = f2fma(HALF2, e2, npxy[p]);
            const F2 snn  = f2add(npxx[p], npyy[p]);         // = -(pxx+pyy) = -eezz
            const F2 ltr  = f2mul(LAM2, f2add(e0, e1));      // tr(ee) = e0+e1 exactly
            const F2 sxx  = f2fma(TWOMU2,  eexx, ltr);
            const F2 syy  = f2fma(TWOMU2,  eeyy, ltr);
            const F2 szz  = f2fma(NTWOMU2, snn,  ltr);
            const F2 sxy  = f2mul(TWOMU2,  eexy);

            const F2 npm = f2mul(f2add(f2add(sxx, syy), szz), NTHIRD2);  // -pressure
            const F2 dxx = f2add(sxx, npm);
            const F2 dyy = f2add(syy, npm);

            // q^2 = 3*(dxx^2 + dyy^2 + dxx*dyy + sxy^2)
            F2 u = f2mul(sxy, sxy);
            u = f2fma(dxx, dyy, u);
            u = f2fma(dyy, dyy, u);
            u = f2fma(dxx, dxx, u);
            const F2 s2c = f2mul(THREE2, u);
            const F2 ys2 = f2fma(H2, al2[p], SIGY2);         // current yield stress

            // ---- scalar radial return per slot (MUFU + FMNMX) ----
            float s_lo, s_hi, ys_lo, ys_hi;
            f2unpack(s2c, s_lo, s_hi);
            f2unpack(ys2, ys_lo, ys_hi);
            s_lo = fmaxf(s_lo, 1e-24f);
            s_hi = fmaxf(s_hi, 1e-24f);
            const float r_lo = rsqrtf(s_lo);
            const float r_hi = rsqrtf(s_hi);
            const float q_lo = s_lo * r_lo;
            const float q_hi = s_hi * r_hi;
            const float dg_lo = fmaxf(q_lo - ys_lo, 0.0f) * KINV_F;
            const float dg_hi = fmaxf(q_hi - ys_hi, 0.0f) * KINV_F;
            const float nc_lo = (-1.5f * dg_lo) * r_lo;      // -1.5*dgam/q
            const float nc_hi = (-1.5f * dg_hi) * r_hi;

            const F2 dg2 = f2pack(dg_lo, dg_hi);
            const F2 nc2 = f2pack(nc_lo, nc_hi);

            al2[p] = f2add(al2[p], dg2);

            // commit plastic strain (negated state: np -= c*d  ->  np = fma(nc, d, np))
            npxx[p] = f2fma(nc2, dxx, npxx[p]);
            npyy[p] = f2fma(nc2, dyy, npyy[p]);
            npxy[p] = f2fma(nc2, sxy, npxy[p]);

            // corrected stress: o = s - 2mu*c*d = fma(2mu*nc, d, s)
            const F2 tmnc = f2mul(TWOMU2, nc2);
            const F2 oxx  = f2fma(tmnc, dxx, sxx);
            const F2 oyy  = f2fma(tmnc, dyy, syy);
            const F2 oxy  = f2fma(tmnc, sxy, sxy);

            // fc2 partial (softplus weights), packed accumulate
            a0 = f2fma(oxx, w2p[p][0][0], f2fma(oyy, w2p[p][0][1], f2fma(oxy, w2p[p][0][2], a0)));
            a1 = f2fma(oxx, w2p[p][1][0], f2fma(oyy, w2p[p][1][1], f2fma(oxy, w2p[p][1][2], a1)));
            a2 = f2fma(oxx, w2p[p][2][0], f2fma(oyy, w2p[p][2][1], f2fma(oxy, w2p[p][2][2], a2)));
        }

        // collapse packed pair slots, then reduce the 4-lane group
        float a0l, a0h, a1l, a1h, a2l, a2h;
        f2unpack(a0, a0l, a0h);
        f2unpack(a1, a1l, a1h);
        f2unpack(a2, a2l, a2h);
        float r0 = a0l + a0h, r1 = a1l + a1h, r2 = a2l + a2h;

        r0 += __shfl_xor_sync(0xffffffffu, r0, 1);
        r1 += __shfl_xor_sync(0xffffffffu, r1, 1);
        r2 += __shfl_xor_sync(0xffffffffu, r2, 1);
        r0 += __shfl_xor_sync(0xffffffffu, r0, 2);
        r1 += __shfl_xor_sync(0xffffffffu, r1, 2);
        r2 += __shfl_xor_sync(0xffffffffu, r2, 2);

        // lanes 0..2 each store one component
        const float oval = (sub == 0) ? r0 : ((sub == 1) ? r1 : r2);
        if (sub < 3) op[3 * t + sub] = oval;

        ex = nex; ey = ney; eg = neg_;
    }
}

extern "C" void kernel_launch(void* const* d_in, const int* in_sizes, int n_in,
                              void* d_out, int out_size)
{
    const float* x  = (const float*)d_in[0];   // [B, T, 3]
    const float* W1 = (const float*)d_in[1];   // [48, 3]
    const float* W2 = (const float*)d_in[2];   // [3, 48]
    float* out      = (float*)d_out;           // [B, T, 3]

    const int B = in_sizes[0] / (T_STEPS * 3);
    const int total_threads = B * TPB;
    const int grid = (total_threads + BLOCK - 1) / BLOCK;

    prnn_j2_kernel<<<grid, BLOCK>>>(x, W1, W2, out, B);
}

// round 7
// speedup vs baseline: 1.2707x; 1.0465x over previous
#include <cuda_runtime.h>
#include <math.h>

// Problem constants (fixed by reference)
#define T_STEPS 128
#define MATPTS  16
#define PPT     2                    // material points per thread (1 packed pair)
#define TPB     (MATPTS / PPT)       // threads per batch element = 8
#define BLOCK   128

// Material constants, derived in double precision at compile time
static constexpr double E_MOD_D = 3130.0;
static constexpr double NU_D    = 0.37;
static constexpr double MU_D    = E_MOD_D / (2.0 * (1.0 + NU_D));
static constexpr double LAM_D   = E_MOD_D * NU_D / ((1.0 + NU_D) * (1.0 - 2.0 * NU_D));
static constexpr double SIGY_D  = 64.8;
static constexpr double H_D     = 300.0;

static constexpr float TWO_MU_F = (float)(2.0 * MU_D);
static constexpr float LAM_F    = (float)LAM_D;
static constexpr float SIGY_F   = (float)SIGY_D;
static constexpr float H_F      = (float)H_D;
static constexpr float KINV_F   = (float)(1.0 / (3.0 * MU_D + H_D));

// ---- packed fp32x2 helpers (sm_100+ only; FFMA2/FADD2/FMUL2 in SASS) ------
typedef unsigned long long u64t;
struct F2 { u64t v; };

__device__ __forceinline__ F2 f2pack(float lo, float hi) {
    F2 r; asm("mov.b64 %0, {%1, %2};" : "=l"(r.v) : "f"(lo), "f"(hi)); return r;
}
__device__ __forceinline__ void f2unpack(F2 a, float& lo, float& hi) {
    asm("mov.b64 {%0, %1}, %2;" : "=f"(lo), "=f"(hi) : "l"(a.v));
}
__device__ __forceinline__ F2 f2fma(F2 a, F2 b, F2 c) {
    F2 r; asm("fma.rn.f32x2 %0, %1, %2, %3;" : "=l"(r.v) : "l"(a.v), "l"(b.v), "l"(c.v)); return r;
}
__device__ __forceinline__ F2 f2add(F2 a, F2 b) {
    F2 r; asm("add.rn.f32x2 %0, %1, %2;" : "=l"(r.v) : "l"(a.v), "l"(b.v)); return r;
}
__device__ __forceinline__ F2 f2mul(F2 a, F2 b) {
    F2 r; asm("mul.rn.f32x2 %0, %1, %2;" : "=l"(r.v) : "l"(a.v), "l"(b.v)); return r;
}
__device__ __forceinline__ F2 f2zero() { F2 r; r.v = 0ULL; return r; }

__global__ void __launch_bounds__(BLOCK)
prnn_j2_kernel(const float* __restrict__ x,
               const float* __restrict__ W1,
               const float* __restrict__ W2,
               float* __restrict__ out,
               int B)
{
    const int tid = blockIdx.x * BLOCK + threadIdx.x;
    const int b   = tid >> 3;           // batch element
    const int sub = tid & 7;            // sub-lane within the 8-thread group
    if (b >= B) return;

    // ---- Packed per-thread weight slices --------------------------------
    // Thread handles material points (2*sub, 2*sub+1) packed into lo/hi slots.
    const int mlo = sub * PPT;
    F2 w1p[3][3];   // eps_j = sum_f x_f * W1[3m+j, f]
    F2 w2p[3][3];   // softplus(W2[o, 3m+j])
    #pragma unroll
    for (int j = 0; j < 3; ++j)
        #pragma unroll
        for (int f = 0; f < 3; ++f)
            w1p[j][f] = f2pack(__ldg(&W1[(3 * mlo + j) * 3 + f]),
                               __ldg(&W1[(3 * (mlo + 1) + j) * 3 + f]));
    #pragma unroll
    for (int o = 0; o < 3; ++o)
        #pragma unroll
        for (int j = 0; j < 3; ++j) {
            float wl = __ldg(&W2[o * 48 + 3 * mlo + j]);
            float wh = __ldg(&W2[o * 48 + 3 * (mlo + 1) + j]);
            w2p[o][j] = f2pack(log1pf(expf(wl)), log1pf(expf(wh)));
        }

    // ---- Packed constants ------------------------------------------------
    const F2 TWOMU2  = f2pack(TWO_MU_F,  TWO_MU_F);
    const F2 NTWOMU2 = f2pack(-TWO_MU_F, -TWO_MU_F);
    const F2 LAM2    = f2pack(LAM_F,     LAM_F);
    const F2 HALF2   = f2pack(0.5f,      0.5f);
    const F2 NTHIRD2 = f2pack(-1.0f/3.0f, -1.0f/3.0f);
    const F2 THREE2  = f2pack(3.0f,      3.0f);
    const F2 H2      = f2pack(H_F,       H_F);
    const F2 SIGY2   = f2pack(SIGY_F,    SIGY_F);
    const F2 TINY2   = f2pack(1e-24f,    1e-24f);

    // ---- Committed history, negated & packed (npxx = -pxx etc.) ----------
    // pzz eliminated (traceless flow: pzz = -(pxx+pyy)).
    F2 npxx = f2zero(), npyy = f2zero(), npxy = f2zero(), al2 = f2zero();

    const float* xp = x   + (size_t)b * (T_STEPS * 3);
    float*       op = out + (size_t)b * (T_STEPS * 3);

    // software-pipelined x loads
    float ex = xp[0], ey = xp[1], eg = xp[2];

    #pragma unroll 1
    for (int t = 0; t < T_STEPS; ++t) {
        float nex = 0.f, ney = 0.f, neg_ = 0.f;
        if (t + 1 < T_STEPS) {
            nex  = xp[3 * t + 3];
            ney  = xp[3 * t + 4];
            neg_ = xp[3 * t + 5];
        }

        const F2 ex2 = f2pack(ex, ex);
        const F2 ey2 = f2pack(ey, ey);
        const F2 eg2 = f2pack(eg, eg);

        // fc1: per-point strain (packed across the pair)
        const F2 e0 = f2fma(ex2, w1p[0][0], f2fma(ey2, w1p[0][1], f2mul(eg2, w1p[0][2])));
        const F2 e1 = f2fma(ex2, w1p[1][0], f2fma(ey2, w1p[1][1], f2mul(eg2, w1p[1][2])));
        const F2 e2 = f2fma(ex2, w1p[2][0], f2fma(ey2, w1p[2][1], f2mul(eg2, w1p[2][2])));

        // elastic predictor (state negated: eexx = e0 + npxx)
        const F2 eexx = f2add(e0, npxx);
        const F2 eeyy = f2add(e1, npyy);
        const F2 eexy = f2fma(HALF2, e2, npxy);
        const F2 snn  = f2add(npxx, npyy);           // = -(pxx+pyy) = -eezz
        const F2 ltr  = f2mul(LAM2, f2add(e0, e1));  // tr(ee) = e0+e1 exactly
        const F2 sxx  = f2fma(TWOMU2,  eexx, ltr);
        const F2 syy  = f2fma(TWOMU2,  eeyy, ltr);
        const F2 szz  = f2fma(NTWOMU2, snn,  ltr);
        const F2 sxy  = f2mul(TWOMU2,  eexy);

        const F2 npm = f2mul(f2add(f2add(sxx, syy), szz), NTHIRD2);  // -pressure
        const F2 dxx = f2add(sxx, npm);
        const F2 dyy = f2add(syy, npm);

        // q^2 = 3*(dxx^2 + dyy^2 + dxx*dyy + sxy^2)   (seeded with tiny guard)
        F2 u = f2fma(sxy, sxy, TINY2);
        u = f2fma(dxx, dyy, u);
        u = f2fma(dyy, dyy, u);
        u = f2fma(dxx, dxx, u);
        const F2 s2c = f2mul(THREE2, u);
        const F2 ys2 = f2fma(H2, al2, SIGY2);        // current yield stress

        // ---- scalar radial return per slot (MUFU + FMNMX) ----
        float s_lo, s_hi, ys_lo, ys_hi;
        f2unpack(s2c, s_lo, s_hi);
        f2unpack(ys2, ys_lo, ys_hi);
        const float r_lo = rsqrtf(s_lo);
        const float r_hi = rsqrtf(s_hi);
        const float q_lo = s_lo * r_lo;
        const float q_hi = s_hi * r_hi;
        const float dg_lo = fmaxf(q_lo - ys_lo, 0.0f) * KINV_F;
        const float dg_hi = fmaxf(q_hi - ys_hi, 0.0f) * KINV_F;
        const float nc_lo = (-1.5f * dg_lo) * r_lo;  // -1.5*dgam/q
        const float nc_hi = (-1.5f * dg_hi) * r_hi;

        const F2 dg2 = f2pack(dg_lo, dg_hi);
        const F2 nc2 = f2pack(nc_lo, nc_hi);

        al2 = f2add(al2, dg2);

        // commit plastic strain (negated state: np = fma(nc, d, np))
        npxx = f2fma(nc2, dxx, npxx);
        npyy = f2fma(nc2, dyy, npyy);
        npxy = f2fma(nc2, sxy, npxy);

        // corrected stress: o = s - 2mu*c*d = fma(2mu*nc, d, s)
        const F2 tmnc = f2mul(TWOMU2, nc2);
        const F2 oxx  = f2fma(tmnc, dxx, sxx);
        const F2 oyy  = f2fma(tmnc, dyy, syy);
        const F2 oxy  = f2fma(tmnc, sxy, sxy);

        // fc2 partial (softplus weights), packed accumulate
        const F2 a0 = f2fma(oxx, w2p[0][0], f2fma(oyy, w2p[0][1], f2mul(oxy, w2p[0][2])));
        const F2 a1 = f2fma(oxx, w2p[1][0], f2fma(oyy, w2p[1][1], f2mul(oxy, w2p[1][2])));
        const F2 a2 = f2fma(oxx, w2p[2][0], f2fma(oyy, w2p[2][1], f2mul(oxy, w2p[2][2])));

        // collapse packed pair slots, then reduce the 8-lane group
        float a0l, a0h, a1l, a1h, a2l, a2h;
        f2unpack(a0, a0l, a0h);
        f2unpack(a1, a1l, a1h);
        f2unpack(a2, a2l, a2h);
        float r0 = a0l + a0h, r1 = a1l + a1h, r2 = a2l + a2h;

        r0 += __shfl_xor_sync(0xffffffffu, r0, 1);
        r1 += __shfl_xor_sync(0xffffffffu, r1, 1);
        r2 += __shfl_xor_sync(0xffffffffu, r2, 1);
        r0 += __shfl_xor_sync(0xffffffffu, r0, 2);
        r1 += __shfl_xor_sync(0xffffffffu, r1, 2);
        r2 += __shfl_xor_sync(0xffffffffu, r2, 2);
        r0 += __shfl_xor_sync(0xffffffffu, r0, 4);
        r1 += __shfl_xor_sync(0xffffffffu, r1, 4);
        r2 += __shfl_xor_sync(0xffffffffu, r2, 4);

        // lanes 0..2 each store one component
        const float oval = (sub == 0) ? r0 : ((sub == 1) ? r1 : r2);
        if (sub < 3) op[3 * t + sub] = oval;

        ex = nex; ey = ney; eg = neg_;
    }
}

extern "C" void kernel_launch(void* const* d_in, const int* in_sizes, int n_in,
                              void* d_out, int out_size)
{
    const float* x  = (const float*)d_in[0];   // [B, T, 3]
    const float* W1 = (const float*)d_in[1];   // [48, 3]
    const float* W2 = (const float*)d_in[2];   // [3, 48]
    float* out      = (float*)d_out;           // [B, T, 3]

    const int B = in_sizes[0] / (T_STEPS * 3);
    const int total_threads = B * TPB;
    const int grid = (total_threads + BLOCK - 1) / BLOCK;

    prnn_j2_kernel<<<grid, BLOCK>>>(x, W1, W2, out, B);
}

// round 8
// speedup vs baseline: 1.4149x; 1.1135x over previous
#include <cuda_runtime.h>
#include <math.h>

// Problem constants (fixed by reference)
#define T_STEPS 128
#define MATPTS  16
#define PPT     2                    // material points per thread (1 packed pair)
#define TPB     (MATPTS / PPT)       // threads per batch element = 8
#define BLOCK   128

// Material constants, derived in double precision at compile time
static constexpr double E_MOD_D = 3130.0;
static constexpr double NU_D    = 0.37;
static constexpr double MU_D    = E_MOD_D / (2.0 * (1.0 + NU_D));
static constexpr double LAM_D   = E_MOD_D * NU_D / ((1.0 + NU_D) * (1.0 - 2.0 * NU_D));
static constexpr double SIGY_D  = 64.8;
static constexpr double H_D     = 300.0;

static constexpr float TWO_MU_F = (float)(2.0 * MU_D);
static constexpr float LAM_F    = (float)LAM_D;
static constexpr float SIGY_F   = (float)SIGY_D;
static constexpr float H_F      = (float)H_D;
static constexpr float KINV_F   = (float)(1.0 / (3.0 * MU_D + H_D));

// ---- packed fp32x2 helpers (sm_100+ only; FFMA2/FADD2/FMUL2 in SASS) ------
typedef unsigned long long u64t;
struct F2 { u64t v; };

__device__ __forceinline__ F2 f2pack(float lo, float hi) {
    F2 r; asm("mov.b64 %0, {%1, %2};" : "=l"(r.v) : "f"(lo), "f"(hi)); return r;
}
__device__ __forceinline__ void f2unpack(F2 a, float& lo, float& hi) {
    asm("mov.b64 {%0, %1}, %2;" : "=f"(lo), "=f"(hi) : "l"(a.v));
}
__device__ __forceinline__ F2 f2fma(F2 a, F2 b, F2 c) {
    F2 r; asm("fma.rn.f32x2 %0, %1, %2, %3;" : "=l"(r.v) : "l"(a.v), "l"(b.v), "l"(c.v)); return r;
}
__device__ __forceinline__ F2 f2add(F2 a, F2 b) {
    F2 r; asm("add.rn.f32x2 %0, %1, %2;" : "=l"(r.v) : "l"(a.v), "l"(b.v)); return r;
}
__device__ __forceinline__ F2 f2mul(F2 a, F2 b) {
    F2 r; asm("mul.rn.f32x2 %0, %1, %2;" : "=l"(r.v) : "l"(a.v), "l"(b.v)); return r;
}
__device__ __forceinline__ F2 f2zero() { F2 r; r.v = 0ULL; return r; }

__global__ void __launch_bounds__(BLOCK, 7)
prnn_j2_kernel(const float* __restrict__ x,
               const float* __restrict__ W1,
               const float* __restrict__ W2,
               float* __restrict__ out,
               int B)
{
    const int tid = blockIdx.x * BLOCK + threadIdx.x;
    const int b   = tid >> 3;           // batch element
    const int sub = tid & 7;            // sub-lane within the 8-thread group
    if (b >= B) return;

    // loop-invariant predicates / routing for the transpose-reduction
    const bool lo4 = (sub < 4);
    const bool lo2 = (sub < 2);
    const bool mid = (sub < 4) && (sub >= 2);
    const bool r2sel = ((sub & 2) != 0);            // within lower half: send r0 on mask-2
    const bool do_store = ((sub & 1) == 0) && (sub < 6);
    const int  comp = sub >> 1;                      // 0,1,2 for lanes 0,2,4

    // ---- Packed per-thread weight slices --------------------------------
    // Thread handles material points (2*sub, 2*sub+1) packed into lo/hi slots.
    const int mlo = sub * PPT;
    F2 w1p[3][3];   // eps_j = sum_f x_f * W1[3m+j, f]
    F2 w2p[3][3];   // softplus(W2[o, 3m+j])
    #pragma unroll
    for (int j = 0; j < 3; ++j)
        #pragma unroll
        for (int f = 0; f < 3; ++f)
            w1p[j][f] = f2pack(__ldg(&W1[(3 * mlo + j) * 3 + f]),
                               __ldg(&W1[(3 * (mlo + 1) + j) * 3 + f]));
    #pragma unroll
    for (int o = 0; o < 3; ++o)
        #pragma unroll
        for (int j = 0; j < 3; ++j) {
            float wl = __ldg(&W2[o * 48 + 3 * mlo + j]);
            float wh = __ldg(&W2[o * 48 + 3 * (mlo + 1) + j]);
            w2p[o][j] = f2pack(log1pf(expf(wl)), log1pf(expf(wh)));
        }

    // ---- Packed constants ------------------------------------------------
    const F2 TWOMU2  = f2pack(TWO_MU_F,  TWO_MU_F);
    const F2 NTWOMU2 = f2pack(-TWO_MU_F, -TWO_MU_F);
    const F2 LAM2    = f2pack(LAM_F,     LAM_F);
    const F2 HALF2   = f2pack(0.5f,      0.5f);
    const F2 NTHIRD2 = f2pack(-1.0f/3.0f, -1.0f/3.0f);
    const F2 THREE2  = f2pack(3.0f,      3.0f);
    const F2 H2      = f2pack(H_F,       H_F);
    const F2 SIGY2   = f2pack(SIGY_F,    SIGY_F);
    const F2 TINY2   = f2pack(1e-24f,    1e-24f);

    // ---- Committed history, negated & packed (npxx = -pxx etc.) ----------
    // pzz eliminated (traceless flow: pzz = -(pxx+pyy)).
    F2 npxx = f2zero(), npyy = f2zero(), npxy = f2zero(), al2 = f2zero();

    const float* xp = x   + (size_t)b * (T_STEPS * 3);
    float*       op = out + (size_t)b * (T_STEPS * 3);

    // software-pipelined x loads
    float ex = xp[0], ey = xp[1], eg = xp[2];

    #pragma unroll 1
    for (int t = 0; t < T_STEPS; ++t) {
        float nex = 0.f, ney = 0.f, neg_ = 0.f;
        if (t + 1 < T_STEPS) {
            nex  = xp[3 * t + 3];
            ney  = xp[3 * t + 4];
            neg_ = xp[3 * t + 5];
        }

        const F2 ex2 = f2pack(ex, ex);
        const F2 ey2 = f2pack(ey, ey);
        const F2 eg2 = f2pack(eg, eg);

        // fc1: per-point strain (packed across the pair)
        const F2 e0 = f2fma(ex2, w1p[0][0], f2fma(ey2, w1p[0][1], f2mul(eg2, w1p[0][2])));
        const F2 e1 = f2fma(ex2, w1p[1][0], f2fma(ey2, w1p[1][1], f2mul(eg2, w1p[1][2])));
        const F2 e2 = f2fma(ex2, w1p[2][0], f2fma(ey2, w1p[2][1], f2mul(eg2, w1p[2][2])));

        // elastic predictor (state negated: eexx = e0 + npxx)
        const F2 eexx = f2add(e0, npxx);
        const F2 eeyy = f2add(e1, npyy);
        const F2 eexy = f2fma(HALF2, e2, npxy);
        const F2 snn  = f2add(npxx, npyy);           // = -(pxx+pyy) = -eezz
        const F2 ltr  = f2mul(LAM2, f2add(e0, e1));  // tr(ee) = e0+e1 exactly
        const F2 sxx  = f2fma(TWOMU2,  eexx, ltr);
        const F2 syy  = f2fma(TWOMU2,  eeyy, ltr);
        const F2 szz  = f2fma(NTWOMU2, snn,  ltr);
        const F2 sxy  = f2mul(TWOMU2,  eexy);

        const F2 npm = f2mul(f2add(f2add(sxx, syy), szz), NTHIRD2);  // -pressure
        const F2 dxx = f2add(sxx, npm);
        const F2 dyy = f2add(syy, npm);

        // q^2 = 3*(dxx^2 + dyy^2 + dxx*dyy + sxy^2)   (seeded with tiny guard)
        F2 u = f2fma(sxy, sxy, TINY2);
        u = f2fma(dxx, dyy, u);
        u = f2fma(dyy, dyy, u);
        u = f2fma(dxx, dxx, u);
        const F2 s2c = f2mul(THREE2, u);
        const F2 ys2 = f2fma(H2, al2, SIGY2);        // current yield stress

        // ---- scalar radial return per slot (MUFU + FMNMX) ----
        float s_lo, s_hi, ys_lo, ys_hi;
        f2unpack(s2c, s_lo, s_hi);
        f2unpack(ys2, ys_lo, ys_hi);
        const float r_lo = rsqrtf(s_lo);
        const float r_hi = rsqrtf(s_hi);
        const float q_lo = s_lo * r_lo;
        const float q_hi = s_hi * r_hi;
        const float dg_lo = fmaxf(q_lo - ys_lo, 0.0f) * KINV_F;
        const float dg_hi = fmaxf(q_hi - ys_hi, 0.0f) * KINV_F;
        const float nc_lo = (-1.5f * dg_lo) * r_lo;  // -1.5*dgam/q
        const float nc_hi = (-1.5f * dg_hi) * r_hi;

        const F2 dg2 = f2pack(dg_lo, dg_hi);
        const F2 nc2 = f2pack(nc_lo, nc_hi);

        al2 = f2add(al2, dg2);

        // commit plastic strain (negated state: np = fma(nc, d, np))
        npxx = f2fma(nc2, dxx, npxx);
        npyy = f2fma(nc2, dyy, npyy);
        npxy = f2fma(nc2, sxy, npxy);

        // corrected stress: o = s - 2mu*c*d = fma(2mu*nc, d, s)
        const F2 tmnc = f2mul(TWOMU2, nc2);
        const F2 oxx  = f2fma(tmnc, dxx, sxx);
        const F2 oyy  = f2fma(tmnc, dyy, syy);
        const F2 oxy  = f2fma(tmnc, sxy, sxy);

        // fc2 partial (softplus weights), packed accumulate
        const F2 a0 = f2fma(oxx, w2p[0][0], f2fma(oyy, w2p[0][1], f2mul(oxy, w2p[0][2])));
        const F2 a1 = f2fma(oxx, w2p[1][0], f2fma(oyy, w2p[1][1], f2mul(oxy, w2p[1][2])));
        const F2 a2 = f2fma(oxx, w2p[2][0], f2fma(oyy, w2p[2][1], f2mul(oxy, w2p[2][2])));

        // collapse packed pair slots
        float a0l, a0h, a1l, a1h, a2l, a2h;
        f2unpack(a0, a0l, a0h);
        f2unpack(a1, a1l, a1h);
        f2unpack(a2, a2l, a2h);
        float r0 = a0l + a0h, r1 = a1l + a1h, r2 = a2l + a2h;

        // ---- transpose-reduction over the 8-lane group: 4 SHFL total ----
        // mask 4, exchange #1: lower half gathers r0, upper half gathers r2
        float v1 = lo4 ? r2 : r0;
        float w1 = __shfl_xor_sync(0xffffffffu, v1, 4);
        if (lo4) r0 += w1; else r2 += w1;
        // mask 4, exchange #2: lower half gathers r1
        float w2 = __shfl_xor_sync(0xffffffffu, r1, 4);
        if (lo4) r1 += w2;
        // mask 2: lanes{0,1} gather r0, lanes{2,3} gather r1, upper gathers r2
        float v3 = lo4 ? (r2sel ? r0 : r1) : r2;
        float w3 = __shfl_xor_sync(0xffffffffu, v3, 2);
        if (lo2)      r0 += w3;
        else if (mid) r1 += w3;
        else          r2 += w3;
        // mask 1: final pairwise; lane0->r0, lane2->r1, lane4->r2
        float v4 = lo2 ? r0 : (lo4 ? r1 : r2);
        float w4 = __shfl_xor_sync(0xffffffffu, v4, 1);
        const float total = v4 + w4;

        // lanes 0,2,4 store components 0,1,2
        if (do_store) op[3 * t + comp] = total;

        ex = nex; ey = ney; eg = neg_;
    }
}

extern "C" void kernel_launch(void* const* d_in, const int* in_sizes, int n_in,
                              void* d_out, int out_size)
{
    const float* x  = (const float*)d_in[0];   // [B, T, 3]
    const float* W1 = (const float*)d_in[1];   // [48, 3]
    const float* W2 = (const float*)d_in[2];   // [3, 48]
    float* out      = (float*)d_out;           // [B, T, 3]

    const int B = in_sizes[0] / (T_STEPS * 3);
    const int total_threads = B * TPB;
    const int grid = (total_threads + BLOCK - 1) / BLOCK;

    prnn_j2_kernel<<<grid, BLOCK>>>(x, W1, W2, out, B);
}

// round 9
// speedup vs baseline: 1.4939x; 1.0558x over previous
#include <cuda_runtime.h>
#include <math.h>

// Problem constants (fixed by reference)
#define T_STEPS 128
#define MATPTS  16
#define PPT     2                    // material points per thread (1 packed pair)
#define TPB     (MATPTS / PPT)       // threads per batch element = 8
#define BLOCK   128

// Material constants, derived in double precision at compile time
static constexpr double E_MOD_D = 3130.0;
static constexpr double NU_D    = 0.37;
static constexpr double MU_D    = E_MOD_D / (2.0 * (1.0 + NU_D));
static constexpr double LAM_D   = E_MOD_D * NU_D / ((1.0 + NU_D) * (1.0 - 2.0 * NU_D));
static constexpr double SIGY_D  = 64.8;
static constexpr double H_D     = 300.0;

static constexpr float TWO_MU_F = (float)(2.0 * MU_D);
static constexpr float K3_F     = (float)(LAM_D + 2.0 * MU_D / 3.0);   // pm = K3*(e0+e1)
static constexpr float NC23_F   = (float)(-2.0 * MU_D / 3.0);          // deviator correction
static constexpr float SIGY_F   = (float)SIGY_D;
static constexpr float H_F      = (float)H_D;
static constexpr float KINV_F   = (float)(1.0 / (3.0 * MU_D + H_D));

// ---- packed fp32x2 helpers (sm_100+ only; FFMA2/FADD2/FMUL2 in SASS) ------
typedef unsigned long long u64t;
struct F2 { u64t v; };

__device__ __forceinline__ F2 f2pack(float lo, float hi) {
    F2 r; asm("mov.b64 %0, {%1, %2};" : "=l"(r.v) : "f"(lo), "f"(hi)); return r;
}
__device__ __forceinline__ void f2unpack(F2 a, float& lo, float& hi) {
    asm("mov.b64 {%0, %1}, %2;" : "=f"(lo), "=f"(hi) : "l"(a.v));
}
__device__ __forceinline__ F2 f2fma(F2 a, F2 b, F2 c) {
    F2 r; asm("fma.rn.f32x2 %0, %1, %2, %3;" : "=l"(r.v) : "l"(a.v), "l"(b.v), "l"(c.v)); return r;
}
__device__ __forceinline__ F2 f2add(F2 a, F2 b) {
    F2 r; asm("add.rn.f32x2 %0, %1, %2;" : "=l"(r.v) : "l"(a.v), "l"(b.v)); return r;
}
__device__ __forceinline__ F2 f2mul(F2 a, F2 b) {
    F2 r; asm("mul.rn.f32x2 %0, %1, %2;" : "=l"(r.v) : "l"(a.v), "l"(b.v)); return r;
}
__device__ __forceinline__ F2 f2zero() { F2 r; r.v = 0ULL; return r; }

__global__ void __launch_bounds__(BLOCK, 7)
prnn_j2_kernel(const float* __restrict__ x,
               const float* __restrict__ W1,
               const float* __restrict__ W2,
               float* __restrict__ out,
               int B)
{
    const int tid = blockIdx.x * BLOCK + threadIdx.x;
    const int b   = tid >> 3;           // batch element
    const int sub = tid & 7;            // sub-lane within the 8-thread group
    if (b >= B) return;

    // loop-invariant predicates / routing for the transpose-reduction
    const bool lo4 = (sub < 4);
    const bool lo2 = (sub < 2);
    const bool mid = (sub < 4) && (sub >= 2);
    const bool r2sel = ((sub & 2) != 0);            // within lower half: send r0 on mask-2
    const bool do_store = ((sub & 1) == 0) && (sub < 6);
    const int  comp = sub >> 1;                      // 0,1,2 for lanes 0,2,4

    // ---- Packed per-thread weight slices --------------------------------
    // Thread handles material points (2*sub, 2*sub+1) packed into lo/hi slots.
    const int mlo = sub * PPT;
    F2 w1p[3][3];   // eps_j = sum_f x_f * W1[3m+j, f]
    F2 w2p[3][3];   // softplus(W2[o, 3m+j])
    #pragma unroll
    for (int j = 0; j < 3; ++j)
        #pragma unroll
        for (int f = 0; f < 3; ++f)
            w1p[j][f] = f2pack(__ldg(&W1[(3 * mlo + j) * 3 + f]),
                               __ldg(&W1[(3 * (mlo + 1) + j) * 3 + f]));
    #pragma unroll
    for (int o = 0; o < 3; ++o)
        #pragma unroll
        for (int j = 0; j < 3; ++j) {
            float wl = __ldg(&W2[o * 48 + 3 * mlo + j]);
            float wh = __ldg(&W2[o * 48 + 3 * (mlo + 1) + j]);
            w2p[o][j] = f2pack(log1pf(expf(wl)), log1pf(expf(wh)));
        }

    // ---- Packed constants ------------------------------------------------
    const F2 TWOMU2 = f2pack(TWO_MU_F, TWO_MU_F);
    const F2 HALF2  = f2pack(0.5f,     0.5f);
    const F2 K32    = f2pack(K3_F,     K3_F);      // pressure coefficient
    const F2 NC232  = f2pack(NC23_F,   NC23_F);    // -2mu/3
    const F2 THREE2 = f2pack(3.0f,     3.0f);
    const F2 NH2    = f2pack(-H_F,     -H_F);
    const F2 NSIGY2 = f2pack(-SIGY_F,  -SIGY_F);
    const F2 KINV2  = f2pack(KINV_F,   KINV_F);
    const F2 N152   = f2pack(-1.5f,    -1.5f);
    const F2 ONE2   = f2pack(1.0f,     1.0f);
    const F2 TINY2  = f2pack(1e-24f,   1e-24f);

    // ---- Committed history, negated & packed (npxx = -pxx etc.) ----------
    // pzz eliminated (traceless flow: pzz = -(pxx+pyy)).
    F2 npxx = f2zero(), npyy = f2zero(), npxy = f2zero(), al2 = f2zero();

    const float* xp = x   + (size_t)b * (T_STEPS * 3);
    float*       op = out + (size_t)b * (T_STEPS * 3);

    // software-pipelined x loads
    float ex = xp[0], ey = xp[1], eg = xp[2];

    #pragma unroll 1
    for (int t = 0; t < T_STEPS; ++t) {
        float nex = 0.f, ney = 0.f, neg_ = 0.f;
        if (t + 1 < T_STEPS) {
            nex  = xp[3 * t + 3];
            ney  = xp[3 * t + 4];
            neg_ = xp[3 * t + 5];
        }

        const F2 ex2 = f2pack(ex, ex);
        const F2 ey2 = f2pack(ey, ey);
        const F2 eg2 = f2pack(eg, eg);

        // fc1: per-point strain (packed across the pair)
        const F2 e0 = f2fma(ex2, w1p[0][0], f2fma(ey2, w1p[0][1], f2mul(eg2, w1p[0][2])));
        const F2 e1 = f2fma(ex2, w1p[1][0], f2fma(ey2, w1p[1][1], f2mul(eg2, w1p[1][2])));
        const F2 e2 = f2fma(ex2, w1p[2][0], f2fma(ey2, w1p[2][1], f2mul(eg2, w1p[2][2])));

        // elastic predictor, deviatoric form (state negated: eexx = e0 + npxx)
        // tr(ee) = e0 + e1 exactly (plane strain + traceless plastic flow)
        const F2 eexx = f2add(e0, npxx);
        const F2 eeyy = f2add(e1, npyy);
        const F2 eexy = f2fma(HALF2, e2, npxy);
        const F2 t01  = f2add(e0, e1);
        const F2 pm   = f2mul(K32,  t01);      // hydrostatic pressure
        const F2 nctr = f2mul(NC232, t01);     // -(2mu/3)*tr
        const F2 dxx  = f2fma(TWOMU2, eexx, nctr);
        const F2 dyy  = f2fma(TWOMU2, eeyy, nctr);
        const F2 sxy  = f2mul(TWOMU2, eexy);

        // q^2 = 3*(dxx^2 + dyy^2 + dxx*dyy + sxy^2)   (seeded with tiny guard)
        F2 u = f2fma(sxy, sxy, TINY2);
        u = f2fma(dxx, dyy, u);
        u = f2fma(dyy, dyy, u);
        u = f2fma(dxx, dxx, u);
        const F2 s2c  = f2mul(THREE2, u);
        const F2 nys2 = f2fma(NH2, al2, NSIGY2);   // -(sigy + H*alpha)

        // ---- radial return: only rsqrt + clamp are scalar ----
        float s_lo, s_hi;
        f2unpack(s2c, s_lo, s_hi);
        const F2 r2p = f2pack(rsqrtf(s_lo), rsqrtf(s_hi));
        const F2 q2  = f2mul(s2c, r2p);            // q (since r = 1/q scaling)
        const F2 fk2 = f2mul(f2add(q2, nys2), KINV2);
        float fk_lo, fk_hi;
        f2unpack(fk2, fk_lo, fk_hi);
        const F2 dg2 = f2pack(fmaxf(fk_lo, 0.0f), fmaxf(fk_hi, 0.0f));
        al2 = f2add(al2, dg2);
        const F2 nc2 = f2mul(f2mul(dg2, N152), r2p);   // -1.5*dgam/q

        // commit plastic strain (negated state: np = fma(nc, d, np))
        npxx = f2fma(nc2, dxx, npxx);
        npyy = f2fma(nc2, dyy, npyy);
        npxy = f2fma(nc2, sxy, npxy);

        // corrected stress: o = d*(1 - 2mu*c) + pm  (wf = 1 + 2mu*nc)
        const F2 wf  = f2fma(TWOMU2, nc2, ONE2);
        const F2 oxx = f2fma(dxx, wf, pm);
        const F2 oyy = f2fma(dyy, wf, pm);
        const F2 oxy = f2mul(sxy, wf);

        // fc2 partial (softplus weights), packed accumulate
        const F2 a0 = f2fma(oxx, w2p[0][0], f2fma(oyy, w2p[0][1], f2mul(oxy, w2p[0][2])));
        const F2 a1 = f2fma(oxx, w2p[1][0], f2fma(oyy, w2p[1][1], f2mul(oxy, w2p[1][2])));
        const F2 a2 = f2fma(oxx, w2p[2][0], f2fma(oyy, w2p[2][1], f2mul(oxy, w2p[2][2])));

        // collapse packed pair slots
        float a0l, a0h, a1l, a1h, a2l, a2h;
        f2unpack(a0, a0l, a0h);
        f2unpack(a1, a1l, a1h);
        f2unpack(a2, a2l, a2h);
        float r0 = a0l + a0h, r1 = a1l + a1h, r2 = a2l + a2h;

        // ---- transpose-reduction over the 8-lane group: 4 SHFL total ----
        // mask 4, exchange #1: lower half gathers r0, upper half gathers r2
        float v1 = lo4 ? r2 : r0;
        float w1 = __shfl_xor_sync(0xffffffffu, v1, 4);
        if (lo4) r0 += w1; else r2 += w1;
        // mask 4, exchange #2: lower half gathers r1
        float w2 = __shfl_xor_sync(0xffffffffu, r1, 4);
        if (lo4) r1 += w2;
        // mask 2: lanes{0,1} gather r0, lanes{2,3} gather r1, upper gathers r2
        float v3 = lo4 ? (r2sel ? r0 : r1) : r2;
        float w3 = __shfl_xor_sync(0xffffffffu, v3, 2);
        if (lo2)      r0 += w3;
        else if (mid) r1 += w3;
        else          r2 += w3;
        // mask 1: final pairwise; lane0->r0, lane2->r1, lane4->r2
        float v4 = lo2 ? r0 : (lo4 ? r1 : r2);
        float w4 = __shfl_xor_sync(0xffffffffu, v4, 1);
        const float total = v4 + w4;

        // lanes 0,2,4 store components 0,1,2
        if (do_store) op[3 * t + comp] = total;

        ex = nex; ey = ney; eg = neg_;
    }
}

extern "C" void kernel_launch(void* const* d_in, const int* in_sizes, int n_in,
                              void* d_out, int out_size)
{
    const float* x  = (const float*)d_in[0];   // [B, T, 3]
    const float* W1 = (const float*)d_in[1];   // [48, 3]
    const float* W2 = (const float*)d_in[2];   // [3, 48]
    float* out      = (float*)d_out;           // [B, T, 3]

    const int B = in_sizes[0] / (T_STEPS * 3);
    const int total_threads = B * TPB;
    const int grid = (total_threads + BLOCK - 1) / BLOCK;

    prnn_j2_kernel<<<grid, BLOCK>>>(x, W1, W2, out, B);
}

// round 11
// speedup vs baseline: 1.6109x; 1.0783x over previous
#include <cuda_runtime.h>
#include <math.h>

// Problem constants (fixed by reference)
#define T_STEPS 128
#define MATPTS  16
#define PPT     2                    // material points per thread (1 packed pair)
#define TPB     (MATPTS / PPT)       // threads per batch element = 8
#define BLOCK   128

// Material constants, derived in double precision at compile time
static constexpr double E_MOD_D = 3130.0;
static constexpr double NU_D    = 0.37;
static constexpr double MU_D    = E_MOD_D / (2.0 * (1.0 + NU_D));
static constexpr double LAM_D   = E_MOD_D * NU_D / ((1.0 + NU_D) * (1.0 - 2.0 * NU_D));
static constexpr double SIGY_D  = 64.8;
static constexpr double H_D     = 300.0;

static constexpr float TWO_MU_F = (float)(2.0 * MU_D);
static constexpr float K3_F     = (float)(LAM_D + 2.0 * MU_D / 3.0);   // pm = K3*(e0+e1)
static constexpr float NC23_F   = (float)(-2.0 * MU_D / 3.0);          // deviator correction
static constexpr float SIGY_F   = (float)SIGY_D;
static constexpr float H_F      = (float)H_D;
static constexpr float KINV_F   = (float)(1.0 / (3.0 * MU_D + H_D));

// ---- packed fp32x2 helpers (sm_100+ only) ---------------------------------
// NOTE: only fma.rn/add.rn/mul.rn exist in the f32x2 PTX family. No max.f32x2.
typedef unsigned long long u64t;
struct F2 { u64t v; };

__device__ __forceinline__ F2 f2pack(float lo, float hi) {
    F2 r; asm("mov.b64 %0, {%1, %2};" : "=l"(r.v) : "f"(lo), "f"(hi)); return r;
}
__device__ __forceinline__ void f2unpack(F2 a, float& lo, float& hi) {
    asm("mov.b64 {%0, %1}, %2;" : "=f"(lo), "=f"(hi) : "l"(a.v));
}
__device__ __forceinline__ F2 f2fma(F2 a, F2 b, F2 c) {
    F2 r; asm("fma.rn.f32x2 %0, %1, %2, %3;" : "=l"(r.v) : "l"(a.v), "l"(b.v), "l"(c.v)); return r;
}
__device__ __forceinline__ F2 f2add(F2 a, F2 b) {
    F2 r; asm("add.rn.f32x2 %0, %1, %2;" : "=l"(r.v) : "l"(a.v), "l"(b.v)); return r;
}
__device__ __forceinline__ F2 f2mul(F2 a, F2 b) {
    F2 r; asm("mul.rn.f32x2 %0, %1, %2;" : "=l"(r.v) : "l"(a.v), "l"(b.v)); return r;
}
// relu on both packed halves (no NaN inputs here): unpack -> fmaxf -> pack
__device__ __forceinline__ F2 f2relu(F2 a) {
    float lo, hi; f2unpack(a, lo, hi);
    return f2pack(fmaxf(lo, 0.0f), fmaxf(hi, 0.0f));
}
__device__ __forceinline__ F2 f2zero() { F2 r; r.v = 0ULL; return r; }

__global__ void __launch_bounds__(BLOCK, 6)
prnn_j2_kernel(const float* __restrict__ x,
               const float* __restrict__ W1,
               const float* __restrict__ W2,
               float* __restrict__ out,
               int B)
{
    const int tid = blockIdx.x * BLOCK + threadIdx.x;
    const int b   = tid >> 3;           // batch element
    const int sub = tid & 7;            // sub-lane within the 8-thread group
    if (b >= B) return;

    // loop-invariant predicates / routing for the transpose-reduction
    const bool lo4 = (sub < 4);
    const bool lo2 = (sub < 2);
    const bool mid = (sub < 4) && (sub >= 2);
    const bool r2sel = ((sub & 2) != 0);
    const bool do_store = ((sub & 1) == 0) && (sub < 6);
    const int  comp = sub >> 1;

    // ---- Packed per-thread weight slices --------------------------------
    const int mlo = sub * PPT;
    F2 w1p[3][3];
    F2 w2p[3][3];
    #pragma unroll
    for (int j = 0; j < 3; ++j)
        #pragma unroll
        for (int f = 0; f < 3; ++f)
            w1p[j][f] = f2pack(__ldg(&W1[(3 * mlo + j) * 3 + f]),
                               __ldg(&W1[(3 * (mlo + 1) + j) * 3 + f]));
    #pragma unroll
    for (int o = 0; o < 3; ++o)
        #pragma unroll
        for (int j = 0; j < 3; ++j) {
            float wl = __ldg(&W2[o * 48 + 3 * mlo + j]);
            float wh = __ldg(&W2[o * 48 + 3 * (mlo + 1) + j]);
            w2p[o][j] = f2pack(log1pf(expf(wl)), log1pf(expf(wh)));
        }

    // ---- Packed constants ------------------------------------------------
    const F2 TWOMU2 = f2pack(TWO_MU_F, TWO_MU_F);
    const F2 HALF2  = f2pack(0.5f,     0.5f);
    const F2 K32    = f2pack(K3_F,     K3_F);
    const F2 NC232  = f2pack(NC23_F,   NC23_F);
    const F2 THREE2 = f2pack(3.0f,     3.0f);
    const F2 NH2    = f2pack(-H_F,     -H_F);
    const F2 NSIGY2 = f2pack(-SIGY_F,  -SIGY_F);
    const F2 KINV2  = f2pack(KINV_F,   KINV_F);
    const F2 N152   = f2pack(-1.5f,    -1.5f);
    const F2 ONE2   = f2pack(1.0f,     1.0f);
    const F2 TINY2  = f2pack(1e-24f,   1e-24f);

    // ---- Committed history (negated, packed) -----------------------------
    F2 npxx = f2zero(), npyy = f2zero(), npxy = f2zero(), al2 = f2zero();

    const float2* xq = (const float2*)(x + (size_t)b * (T_STEPS * 3));
    float*        opc = out + (size_t)b * (T_STEPS * 3) + comp;

    // one step of the J2 update + fc2 + transpose-reduction + store
    auto step = [&](float ex, float ey, float eg, float* dst) {
        const F2 ex2 = f2pack(ex, ex);
        const F2 ey2 = f2pack(ey, ey);
        const F2 eg2 = f2pack(eg, eg);

        // fc1: per-point strain
        const F2 e0 = f2fma(ex2, w1p[0][0], f2fma(ey2, w1p[0][1], f2mul(eg2, w1p[0][2])));
        const F2 e1 = f2fma(ex2, w1p[1][0], f2fma(ey2, w1p[1][1], f2mul(eg2, w1p[1][2])));
        const F2 e2 = f2fma(ex2, w1p[2][0], f2fma(ey2, w1p[2][1], f2mul(eg2, w1p[2][2])));

        // elastic predictor, deviatoric form (state negated)
        const F2 eexx = f2add(e0, npxx);
        const F2 eeyy = f2add(e1, npyy);
        const F2 eexy = f2fma(HALF2, e2, npxy);
        const F2 t01  = f2add(e0, e1);
        const F2 pm   = f2mul(K32,  t01);
        const F2 nctr = f2mul(NC232, t01);
        const F2 dxx  = f2fma(TWOMU2, eexx, nctr);
        const F2 dyy  = f2fma(TWOMU2, eeyy, nctr);
        const F2 sxy  = f2mul(TWOMU2, eexy);

        // q^2 = 3*(dxx^2 + dxx*dyy + dyy^2 + sxy^2), tree form
        const F2 sd  = f2add(dxx, dyy);
        const F2 A   = f2fma(sxy, sxy, TINY2);
        const F2 p1  = f2mul(dxx, sd);             // dxx^2 + dxx*dyy
        const F2 p2  = f2fma(dyy, dyy, A);
        const F2 s2c = f2mul(THREE2, f2add(p1, p2));
        const F2 nys2 = f2fma(NH2, al2, NSIGY2);   // -(sigy + H*alpha)

        // radial return: only rsqrt + clamp are scalar
        float s_lo, s_hi;
        f2unpack(s2c, s_lo, s_hi);
        const F2 r2p = f2pack(rsqrtf(s_lo), rsqrtf(s_hi));
        const F2 nr2 = f2mul(N152, r2p);           // -1.5/q scale (off chain)
        const F2 q2  = f2mul(s2c, r2p);            // q
        const F2 fk2 = f2mul(f2add(q2, nys2), KINV2);
        const F2 dg2 = f2relu(fk2);
        al2 = f2add(al2, dg2);
        const F2 nc2 = f2mul(dg2, nr2);            // -1.5*dgam/q

        // commit plastic strain
        npxx = f2fma(nc2, dxx, npxx);
        npyy = f2fma(nc2, dyy, npyy);
        npxy = f2fma(nc2, sxy, npxy);

        // corrected stress: o = d*(1 + 2mu*nc) + pm
        const F2 wf  = f2fma(TWOMU2, nc2, ONE2);
        const F2 oxx = f2fma(dxx, wf, pm);
        const F2 oyy = f2fma(dyy, wf, pm);
        const F2 oxy = f2mul(sxy, wf);

        // fc2 partial (softplus weights)
        const F2 a0 = f2fma(oxx, w2p[0][0], f2fma(oyy, w2p[0][1], f2mul(oxy, w2p[0][2])));
        const F2 a1 = f2fma(oxx, w2p[1][0], f2fma(oyy, w2p[1][1], f2mul(oxy, w2p[1][2])));
        const F2 a2 = f2fma(oxx, w2p[2][0], f2fma(oyy, w2p[2][1], f2mul(oxy, w2p[2][2])));

        // collapse packed pair slots
        float a0l, a0h, a1l, a1h, a2l, a2h;
        f2unpack(a0, a0l, a0h);
        f2unpack(a1, a1l, a1h);
        f2unpack(a2, a2l, a2h);
        float r0 = a0l + a0h, r1 = a1l + a1h, r2 = a2l + a2h;

        // transpose-reduction over the 8-lane group: 4 SHFL total
        float v1 = lo4 ? r2 : r0;
        float w1 = __shfl_xor_sync(0xffffffffu, v1, 4);
        if (lo4) r0 += w1; else r2 += w1;
        float w2 = __shfl_xor_sync(0xffffffffu, r1, 4);
        if (lo4) r1 += w2;
        float v3 = lo4 ? (r2sel ? r0 : r1) : r2;
        float w3 = __shfl_xor_sync(0xffffffffu, v3, 2);
        if (lo2)      r0 += w3;
        else if (mid) r1 += w3;
        else          r2 += w3;
        float v4 = lo2 ? r0 : (lo4 ? r1 : r2);
        float w4 = __shfl_xor_sync(0xffffffffu, v4, 1);
        const float total = v4 + w4;

        if (do_store) *dst = total;
    };

    // software-pipelined pair loads (3 x LDG.64 per 2 steps)
    float2 cA = xq[0], cB = xq[1], cC = xq[2];

    #pragma unroll 1
    for (int k = 0; k < T_STEPS / 2; ++k) {
        // clamped prefetch of the next pair (no branch)
        const float2* nq = xq + ((k + 1 < T_STEPS / 2) ? 3 : 0);
        const float2 nA = nq[0], nB = nq[1], nC = nq[2];

        // step 2k: (f0, f1, f2)   step 2k+1: (f3, f4, f5)
        step(cA.x, cA.y, cB.x, opc);
        step(cB.y, cC.x, cC.y, opc + 3);

        cA = nA; cB = nB; cC = nC;
        xq += 3;
        opc += 6;
    }
}

extern "C" void kernel_launch(void* const* d_in, const int* in_sizes, int n_in,
                              void* d_out, int out_size)
{
    const float* x  = (const float*)d_in[0];   // [B, T, 3]
    const float* W1 = (const float*)d_in[1];   // [48, 3]
    const float* W2 = (const float*)d_in[2];   // [3, 48]
    float* out      = (float*)d_out;           // [B, T, 3]

    const int B = in_sizes[0] / (T_STEPS * 3);
    const int total_threads = B * TPB;
    const int grid = (total_threads + BLOCK - 1) / BLOCK;

    prnn_j2_kernel<<<grid, BLOCK>>>(x, W1, W2, out, B);
}